// round 8
// baseline (speedup 1.0000x reference)
#include <cuda_runtime.h>

#define BN   4
#define LL   512
#define HH   768
#define HSZ  64
#define NOUT 16
#define NTOK (BN*LL)      // 2048
#define NP   131328       // L*(L+1)/2
#define NKQ  16           // split-K factor
#define KQ   (HH/NKQ)     // 48

// scratch (allocation-free rule: __device__ globals)
__device__ float g_part[NKQ*NTOK*128]; // 16 MB split-K partials [kq][tok][n]
__device__ float g_q[NTOK*HSZ];        // 512 KB
__device__ float g_k[NTOK*HSZ];        // 512 KB
__device__ float g_A[NTOK*NOUT];       // 128 KB
__device__ float g_E[NTOK*NOUT];       // 128 KB
__device__ float g_S[BN*LL*LL];        // 4 MB
__device__ unsigned short g_row[NP];   // 262 KB: pair index -> s

// ---------------------------------------------------------------------------
// Kernel 1: split-K partial GEMM, occupancy-first shape (R7, unchanged).
// 128-thread blocks; tile = 64 tokens x 64 cols; per-thread 8 tok x 4 col.
// Grid = 32 token-tiles x 2 col-halves (q|k) x 16 K-slices = 1024 blocks.
// ---------------------------------------------------------------------------
__global__ __launch_bounds__(128) void proj_partial_kernel(
    const float* __restrict__ x,
    const float* __restrict__ Wq,
    const float* __restrict__ Wk)
{
    __shared__ float xs[16][68];
    __shared__ float ws[16][64];

    const int tid = threadIdx.x;
    const int bi  = blockIdx.x;
    const int tt  = bi & 31;
    const int cc  = (bi >> 5) & 1;
    const int kq  = bi >> 6;
    const int t0  = tt * 64;
    const int k0  = kq * KQ;
    const float* __restrict__ W = cc ? Wk : Wq;

    const int n0 = (tid & 15) * 4;
    const int m0 = (tid >> 4) * 8;

    float acc[8][4];
    #pragma unroll
    for (int i = 0; i < 8; i++)
        #pragma unroll
        for (int j = 0; j < 4; j++) acc[i][j] = 0.f;

    for (int kk = k0; kk < k0 + KQ; kk += 16) {
        #pragma unroll
        for (int p = 0; p < 8; p++) {
            int e = tid + p * 128;
            int tok = e >> 4, d = e & 15;
            xs[d][tok] = x[(t0 + tok) * HH + kk + d];
        }
        #pragma unroll
        for (int p = 0; p < 8; p++) {
            int e = tid + p * 128;
            int n = e & 63, d = e >> 6;
            ws[d][n] = W[(kk + d) * HSZ + n];
        }
        __syncthreads();
        #pragma unroll
        for (int kd = 0; kd < 16; kd++) {
            float4 a0 = *(const float4*)&xs[kd][m0];
            float4 a1 = *(const float4*)&xs[kd][m0 + 4];
            float4 w0 = *(const float4*)&ws[kd][n0];
            float am[8] = {a0.x, a0.y, a0.z, a0.w, a1.x, a1.y, a1.z, a1.w};
            float wn[4] = {w0.x, w0.y, w0.z, w0.w};
            #pragma unroll
            for (int i = 0; i < 8; i++)
                #pragma unroll
                for (int j = 0; j < 4; j++) acc[i][j] += am[i] * wn[j];
        }
        __syncthreads();
    }

    #pragma unroll
    for (int i = 0; i < 8; i++) {
        float* gp = g_part + ((size_t)kq * NTOK + t0 + m0 + i) * 128 + cc * 64 + n0;
        *(float4*)gp = make_float4(acc[i][0], acc[i][1], acc[i][2], acc[i][3]);
    }
}

// ---------------------------------------------------------------------------
// Kernel 2: reduce split-K partials + bias -> g_q/g_k, A/E tables, AND build
// the pair->row u16 table used by the flattened scatter.
// ---------------------------------------------------------------------------
__global__ __launch_bounds__(256) void reduce_ae_kernel(
    const float* __restrict__ bq, const float* __restrict__ bk,
    const float* __restrict__ bb, const float* __restrict__ Wb)
{
    __shared__ float Wbs[256 * NOUT];
    __shared__ float sQK[32][132];
    __shared__ float bbs[NOUT];
    __shared__ float bqs[HSZ], bks[HSZ];

    const int tid = threadIdx.x;
    const int t0  = blockIdx.x * 32;

    // pair->row table: block bi owns s in [bi*8, bi*8+8)
    {
        int s0 = blockIdx.x * 8;
        for (int s = s0; s < s0 + 8; s++) {
            int bse = (s * (1025 - s)) >> 1;   // base(s) = s*512 - s(s-1)/2
            int nE  = LL - s;
            for (int j = tid; j < nE; j += 256)
                g_row[bse + j] = (unsigned short)s;
        }
    }

    #pragma unroll
    for (int p = 0; p < 16; p++)
        Wbs[tid + p * 256] = Wb[tid + p * 256];
    if (tid < NOUT) bbs[tid] = bb[tid];
    if (tid < HSZ)  { bqs[tid] = bq[tid]; bks[tid] = bk[tid]; }
    __syncthreads();

    const float4* gp4 = (const float4*)g_part;
    #pragma unroll
    for (int p = 0; p < 4; p++) {
        int e  = tid + p * 256;
        int tok = e >> 5, n4 = e & 31;
        size_t gi = (size_t)(t0 + tok) * 32 + n4;
        float4 v = make_float4(0.f, 0.f, 0.f, 0.f);
        #pragma unroll
        for (int q = 0; q < NKQ; q++) {
            float4 pv = gp4[(size_t)q * NTOK * 32 + gi];
            v.x += pv.x; v.y += pv.y; v.z += pv.z; v.w += pv.w;
        }
        int n = n4 * 4;
        if (n < 64) { v.x += bqs[n]; v.y += bqs[n+1]; v.z += bqs[n+2]; v.w += bqs[n+3]; }
        else        { v.x += bks[n-64]; v.y += bks[n-63]; v.z += bks[n-62]; v.w += bks[n-61]; }
        *(float4*)&sQK[tok][n] = v;
        int tok_g = t0 + tok;
        if (n4 < 16) ((float4*)(g_q + tok_g * HSZ))[n4]      = v;
        else         ((float4*)(g_k + tok_g * HSZ))[n4 - 16] = v;
    }
    __syncthreads();

    // A table: 32 tok x 16 o (warp-uniform)
    #pragma unroll
    for (int p = 0; p < 2; p++) {
        int e2   = tid + p * 256;
        int tokL = e2 >> 4;
        int o    = e2 & 15;
        float a = bbs[o];
        #pragma unroll 8
        for (int h = 0; h < 64; h++)
            a += sQK[tokL][h] * Wbs[h * NOUT + o];
        g_A[(t0 + tokL) * NOUT + o] = a;
    }
    // E table
    #pragma unroll
    for (int p = 0; p < 2; p++) {
        int e2   = tid + p * 256;
        int tokL = e2 >> 4;
        int o    = e2 & 15;
        float a = 0.f;
        #pragma unroll 8
        for (int h = 0; h < 64; h++) {
            a += sQK[tokL][64 + h] * (Wbs[(64 + h) * NOUT + o] + Wbs[(192 + h) * NOUT + o]);
            a += sQK[tokL][h]      *  Wbs[(128 + h) * NOUT + o];
        }
        g_E[(t0 + tokL) * NOUT + o] = a;
    }
}

// ---------------------------------------------------------------------------
// Kernel 3: S[b] = Q[b] @ K[b]^T (unchanged). Below-diagonal tiles early-exit.
// ---------------------------------------------------------------------------
__global__ __launch_bounds__(256) void score_kernel()
{
    const int bx = blockIdx.x;
    const int by = blockIdx.y;
    if (by > bx) return;
    const int b  = blockIdx.z;

    __shared__ float qs[64][68];
    __shared__ float ks[64][68];

    const int tid = threadIdx.x;
    const float* qb = g_q + (b * LL + by * 64) * HSZ;
    const float* kb = g_k + (b * LL + bx * 64) * HSZ;

    #pragma unroll
    for (int p = 0; p < 16; p++) {
        int e = tid + p * 256;
        int r = e >> 6, h = e & 63;
        qs[h][r] = qb[r * HSZ + h];
        ks[h][r] = kb[r * HSZ + h];
    }
    __syncthreads();

    const int m0 = (tid >> 4) * 4;
    const int n0 = (tid & 15) * 4;
    float acc[4][4];
    #pragma unroll
    for (int i = 0; i < 4; i++)
        #pragma unroll
        for (int j = 0; j < 4; j++) acc[i][j] = 0.f;

    #pragma unroll
    for (int h = 0; h < 64; h++) {
        float4 a = *(const float4*)&qs[h][m0];
        float4 v = *(const float4*)&ks[h][n0];
        float am[4] = {a.x, a.y, a.z, a.w};
        float vn[4] = {v.x, v.y, v.z, v.w};
        #pragma unroll
        for (int i = 0; i < 4; i++)
            #pragma unroll
            for (int j = 0; j < 4; j++) acc[i][j] += am[i] * vn[j];
    }

    float* Sp = g_S + (size_t)b * LL * LL + (by * 64 + m0) * LL + bx * 64 + n0;
    #pragma unroll
    for (int i = 0; i < 4; i++)
        *(float4*)&Sp[i * LL] = make_float4(acc[i][0], acc[i][1], acc[i][2], acc[i][3]);
}

// ---------------------------------------------------------------------------
// Kernel 4: flattened scatter. Thread t owns float4-column (p, oq) and loops
// over the 4 batches (gid = t + b*NP*4): one index computation amortized over
// 4 independent load/store groups. No smem, no sync, no tail blocks.
// out4[b*NP*4 + p*4 + oq] = S[b,s,e] + A4[(b*512+s)*4+oq] + E4[(b*512+e)*4+oq]
// ---------------------------------------------------------------------------
__global__ __launch_bounds__(256) void scatter_kernel(float* __restrict__ out)
{
    const int t = blockIdx.x * 256 + threadIdx.x;   // 0 .. NP*4-1
    const int p  = t >> 2;
    const int oq = t & 3;

    const int s   = (int)g_row[p];
    const int bse = (s * (1025 - s)) >> 1;
    const int e   = s + (p - bse);

    const float4* A4 = (const float4*)g_A;
    const float4* E4 = (const float4*)g_E;
    float4* out4 = (float4*)out;

    #pragma unroll
    for (int b = 0; b < BN; b++) {
        float  sv = g_S[((size_t)b << 18) + (s << 9) + e];
        float4 av = A4[(b * LL + s) * 4 + oq];
        float4 ev = E4[(b * LL + e) * 4 + oq];
        float4 r  = make_float4(sv + av.x + ev.x, sv + av.y + ev.y,
                                sv + av.z + ev.z, sv + av.w + ev.w);
        __stcs(&out4[(size_t)b * NP * 4 + t], r);
    }
}

extern "C" void kernel_launch(void* const* d_in, const int* in_sizes, int n_in,
                              void* d_out, int out_size)
{
    const float* x  = (const float*)d_in[0];
    const float* Wq = (const float*)d_in[1];
    const float* bq = (const float*)d_in[2];
    const float* Wk = (const float*)d_in[3];
    const float* bk = (const float*)d_in[4];
    const float* Wb = (const float*)d_in[5];
    const float* bb = (const float*)d_in[6];
    float* out = (float*)d_out;

    proj_partial_kernel<<<1024, 128>>>(x, Wq, Wk);
    reduce_ae_kernel<<<64, 256>>>(bq, bk, bb, Wb);
    dim3 g2(LL / 64, LL / 64, BN);
    score_kernel<<<g2, 256>>>();
    scatter_kernel<<<(NP * 4) / 256, 256>>>(out);   // 2052 blocks
}

// round 9
// speedup vs baseline: 1.4417x; 1.4417x over previous
#include <cuda_runtime.h>

#define BN   4
#define LL   512
#define HH   768
#define HSZ  64
#define NOUT 16
#define NTOK (BN*LL)      // 2048
#define NP   131328       // L*(L+1)/2
#define NKQ  16           // split-K factor
#define KQ   (HH/NKQ)     // 48

// scratch (allocation-free rule: __device__ globals)
__device__ float g_part[NKQ*NTOK*128]; // 16 MB split-K partials [kq][tok][n]
__device__ float g_q[NTOK*HSZ];        // 512 KB
__device__ float g_k[NTOK*HSZ];        // 512 KB
__device__ float g_A[NTOK*NOUT];       // 128 KB
__device__ float g_E[NTOK*NOUT];       // 128 KB

// ---------------------------------------------------------------------------
// Kernel 1: split-K partial GEMM (R7 shape, unchanged — best measured).
// 128-thread blocks; tile = 64 tokens x 64 cols; per-thread 8 tok x 4 col.
// Grid = 32 token-tiles x 2 col-halves (q|k) x 16 K-slices = 1024 blocks.
// ---------------------------------------------------------------------------
__global__ __launch_bounds__(128) void proj_partial_kernel(
    const float* __restrict__ x,
    const float* __restrict__ Wq,
    const float* __restrict__ Wk)
{
    __shared__ float xs[16][68];
    __shared__ float ws[16][64];

    const int tid = threadIdx.x;
    const int bi  = blockIdx.x;
    const int tt  = bi & 31;
    const int cc  = (bi >> 5) & 1;
    const int kq  = bi >> 6;
    const int t0  = tt * 64;
    const int k0  = kq * KQ;
    const float* __restrict__ W = cc ? Wk : Wq;

    const int n0 = (tid & 15) * 4;
    const int m0 = (tid >> 4) * 8;

    float acc[8][4];
    #pragma unroll
    for (int i = 0; i < 8; i++)
        #pragma unroll
        for (int j = 0; j < 4; j++) acc[i][j] = 0.f;

    for (int kk = k0; kk < k0 + KQ; kk += 16) {
        #pragma unroll
        for (int p = 0; p < 8; p++) {
            int e = tid + p * 128;
            int tok = e >> 4, d = e & 15;
            xs[d][tok] = x[(t0 + tok) * HH + kk + d];
        }
        #pragma unroll
        for (int p = 0; p < 8; p++) {
            int e = tid + p * 128;
            int n = e & 63, d = e >> 6;
            ws[d][n] = W[(kk + d) * HSZ + n];
        }
        __syncthreads();
        #pragma unroll
        for (int kd = 0; kd < 16; kd++) {
            float4 a0 = *(const float4*)&xs[kd][m0];
            float4 a1 = *(const float4*)&xs[kd][m0 + 4];
            float4 w0 = *(const float4*)&ws[kd][n0];
            float am[8] = {a0.x, a0.y, a0.z, a0.w, a1.x, a1.y, a1.z, a1.w};
            float wn[4] = {w0.x, w0.y, w0.z, w0.w};
            #pragma unroll
            for (int i = 0; i < 8; i++)
                #pragma unroll
                for (int j = 0; j < 4; j++) acc[i][j] += am[i] * wn[j];
        }
        __syncthreads();
    }

    #pragma unroll
    for (int i = 0; i < 8; i++) {
        float* gp = g_part + ((size_t)kq * NTOK + t0 + m0 + i) * 128 + cc * 64 + n0;
        *(float4*)gp = make_float4(acc[i][0], acc[i][1], acc[i][2], acc[i][3]);
    }
}

// ---------------------------------------------------------------------------
// Kernel 2: reduce split-K partials + bias -> g_q/g_k, then A/E tables.
// A[s,o] = q[s]@Wb[0:64] + bb
// E[e,o] = k[e]@(Wb[64:128]+Wb[192:256]) + q[e]@Wb[128:192]
// ---------------------------------------------------------------------------
__global__ __launch_bounds__(256) void reduce_ae_kernel(
    const float* __restrict__ bq, const float* __restrict__ bk,
    const float* __restrict__ bb, const float* __restrict__ Wb)
{
    __shared__ float Wbs[256 * NOUT];
    __shared__ float sQK[32][132];
    __shared__ float bbs[NOUT];
    __shared__ float bqs[HSZ], bks[HSZ];

    const int tid = threadIdx.x;
    const int t0  = blockIdx.x * 32;

    #pragma unroll
    for (int p = 0; p < 16; p++)
        Wbs[tid + p * 256] = Wb[tid + p * 256];
    if (tid < NOUT) bbs[tid] = bb[tid];
    if (tid < HSZ)  { bqs[tid] = bq[tid]; bks[tid] = bk[tid]; }
    __syncthreads();

    const float4* gp4 = (const float4*)g_part;
    #pragma unroll
    for (int p = 0; p < 4; p++) {
        int e  = tid + p * 256;
        int tok = e >> 5, n4 = e & 31;
        size_t gi = (size_t)(t0 + tok) * 32 + n4;
        float4 v = make_float4(0.f, 0.f, 0.f, 0.f);
        #pragma unroll
        for (int q = 0; q < NKQ; q++) {
            float4 pv = gp4[(size_t)q * NTOK * 32 + gi];
            v.x += pv.x; v.y += pv.y; v.z += pv.z; v.w += pv.w;
        }
        int n = n4 * 4;
        if (n < 64) { v.x += bqs[n]; v.y += bqs[n+1]; v.z += bqs[n+2]; v.w += bqs[n+3]; }
        else        { v.x += bks[n-64]; v.y += bks[n-63]; v.z += bks[n-62]; v.w += bks[n-61]; }
        *(float4*)&sQK[tok][n] = v;
        int tok_g = t0 + tok;
        if (n4 < 16) ((float4*)(g_q + tok_g * HSZ))[n4]      = v;
        else         ((float4*)(g_k + tok_g * HSZ))[n4 - 16] = v;
    }
    __syncthreads();

    // A table: 32 tok x 16 o (warp-uniform)
    #pragma unroll
    for (int p = 0; p < 2; p++) {
        int e2   = tid + p * 256;
        int tokL = e2 >> 4;
        int o    = e2 & 15;
        float a = bbs[o];
        #pragma unroll 8
        for (int h = 0; h < 64; h++)
            a += sQK[tokL][h] * Wbs[h * NOUT + o];
        g_A[(t0 + tokL) * NOUT + o] = a;
    }
    // E table
    #pragma unroll
    for (int p = 0; p < 2; p++) {
        int e2   = tid + p * 256;
        int tokL = e2 >> 4;
        int o    = e2 & 15;
        float a = 0.f;
        #pragma unroll 8
        for (int h = 0; h < 64; h++) {
            a += sQK[tokL][64 + h] * (Wbs[(64 + h) * NOUT + o] + Wbs[(192 + h) * NOUT + o]);
            a += sQK[tokL][h]      *  Wbs[(128 + h) * NOUT + o];
        }
        g_E[(t0 + tokL) * NOUT + o] = a;
    }
}

// ---------------------------------------------------------------------------
// Kernel 3: FUSED score + scatter. One block per 64x64 (s-tile, e-tile);
// below-diagonal tiles exit. Computes the S tile into shared, stages the A and
// E tiles (4 KB each) in shared, then streams the final output directly:
// per s-row, 256 threads write 256 consecutive float4 (coalesced STG.128);
// the store loop reads only shared memory. No g_S, no separate scatter pass.
// ---------------------------------------------------------------------------
__global__ __launch_bounds__(256) void score_scatter_kernel(float* __restrict__ out)
{
    const int bx = blockIdx.x;   // e tile
    const int by = blockIdx.y;   // s tile
    if (by > bx) return;
    const int b  = blockIdx.z;

    __shared__ float  qs[64][68];
    __shared__ float  ks[64][68];
    __shared__ float  Ss[64][65];   // S tile [sl][j]
    __shared__ float4 Es[256];      // E tile [j*4+oq]
    __shared__ float4 As[256];      // A tile [sl*4+oq]

    const int tid = threadIdx.x;
    const float* qb = g_q + (b * LL + by * 64) * HSZ;
    const float* kb = g_k + (b * LL + bx * 64) * HSZ;

    #pragma unroll
    for (int p = 0; p < 16; p++) {
        int e = tid + p * 256;
        int r = e >> 6, h = e & 63;
        qs[h][r] = qb[r * HSZ + h];
        ks[h][r] = kb[r * HSZ + h];
    }
    // stage A/E tiles: one float4 per thread, coalesced
    Es[tid] = ((const float4*)g_E)[(b * LL + bx * 64) * 4 + tid];
    As[tid] = ((const float4*)g_A)[(b * LL + by * 64) * 4 + tid];
    __syncthreads();

    // --- compute S tile (4x4 per thread) ---
    const int m0 = (tid >> 4) * 4;
    const int n0 = (tid & 15) * 4;
    float acc[4][4];
    #pragma unroll
    for (int i = 0; i < 4; i++)
        #pragma unroll
        for (int j = 0; j < 4; j++) acc[i][j] = 0.f;

    #pragma unroll
    for (int h = 0; h < 64; h++) {
        float4 a = *(const float4*)&qs[h][m0];
        float4 v = *(const float4*)&ks[h][n0];
        float am[4] = {a.x, a.y, a.z, a.w};
        float vn[4] = {v.x, v.y, v.z, v.w};
        #pragma unroll
        for (int i = 0; i < 4; i++)
            #pragma unroll
            for (int j = 0; j < 4; j++) acc[i][j] += am[i] * vn[j];
    }
    #pragma unroll
    for (int i = 0; i < 4; i++)
        #pragma unroll
        for (int j = 0; j < 4; j++) Ss[m0 + i][n0 + j] = acc[i][j];
    __syncthreads();

    // --- store phase: all operands in shared; stores fully coalesced ---
    const int j  = tid >> 2;        // e offset within tile
    const int oq = tid & 3;
    const bool diag = (bx == by);
    const float4 ev = Es[tid];
    float4* out4 = (float4*)out;
    const size_t bbase = (size_t)b * NP;

    #pragma unroll 4
    for (int sl = 0; sl < 64; sl++) {
        int s  = by * 64 + sl;
        // pair index of (s, e0=bx*64): bse(s) + bx*64 - s, bse(s)=s*(1025-s)/2
        int p0 = ((s * (1025 - s)) >> 1) + bx * 64 - s;
        float  sv = Ss[sl][j];
        float4 av = As[(sl << 2) | oq];
        float4 r  = make_float4(sv + av.x + ev.x, sv + av.y + ev.y,
                                sv + av.z + ev.z, sv + av.w + ev.w);
        if (!diag || j >= sl)
            out4[(bbase + p0) * 4 + tid] = r;
    }
}

extern "C" void kernel_launch(void* const* d_in, const int* in_sizes, int n_in,
                              void* d_out, int out_size)
{
    const float* x  = (const float*)d_in[0];
    const float* Wq = (const float*)d_in[1];
    const float* bq = (const float*)d_in[2];
    const float* Wk = (const float*)d_in[3];
    const float* bk = (const float*)d_in[4];
    const float* Wb = (const float*)d_in[5];
    const float* bb = (const float*)d_in[6];
    float* out = (float*)d_out;

    proj_partial_kernel<<<1024, 128>>>(x, Wq, Wk);
    reduce_ae_kernel<<<64, 256>>>(bq, bk, bb, Wb);
    dim3 g2(LL / 64, LL / 64, BN);
    score_scatter_kernel<<<g2, 256>>>(out);
}